// round 2
// baseline (speedup 1.0000x reference)
#include <cuda_runtime.h>

// gRNN over 1024 complete binary trees, depth 10, hidden SIZE=100.
// Level-synchronous: level d is a GEMM  h_d = relu((h_{2g}+h_{2g+1}) @ Ww^T + Wb + t*Qw + Qb)
// Level 8 fuses leaf construction; level 0 fuses the 5-way output projection.

#define S        100
#define SP       101     // padded smem stride (conflict-free)
#define TM       32      // node rows per CTA
#define NTHREADS 160     // 8 node-groups x 20 out-groups, micro-tile 4x5
#define NTREES   1024
#define NNODES   1023

// Ping-pong level buffers (no runtime allocation allowed).
__device__ float g_bufA[NTREES * 256 * S];   // holds levels 8,6,4,2  (max 26.2M floats)
__device__ float g_bufB[NTREES * 128 * S];   // holds levels 7,5,3,1  (max 13.1M floats)

#define SMEM_BYTES ((S*SP + TM*SP + 3*S) * (int)sizeof(float))

template<bool LEAF, bool ROOT>
__global__ __launch_bounds__(NTHREADS)
void level_kernel(const float* __restrict__ times,
                  const float* __restrict__ Qw,
                  const float* __restrict__ Qb,
                  const float* __restrict__ Ww,
                  const float* __restrict__ Wb,
                  const float* __restrict__ Pw,
                  const float* __restrict__ Pb,
                  const float* __restrict__ prev,
                  float* __restrict__ cur,
                  float* __restrict__ out,
                  int d)
{
    extern __shared__ float sm[];
    float* Ww_s   = sm;                 // [S][SP]
    float* comb_s = Ww_s + S * SP;      // [TM][SP]
    float* Qw_s   = comb_s + TM * SP;   // [S]
    float* Qb_s   = Qw_s + S;           // [S]
    float* Wb_s   = Qb_s + S;           // [S]

    const int tid     = threadIdx.x;
    const int lvl     = 1 << d;
    const int baseRow = blockIdx.x * TM;

    // ---- stage weights ----
    for (int idx = tid; idx < S; idx += NTHREADS) {
        Qw_s[idx] = Qw[idx];
        Qb_s[idx] = Qb[idx];
        Wb_s[idx] = Wb[idx];
    }
    for (int idx = tid; idx < S * S; idx += NTHREADS) {
        Ww_s[(idx / S) * SP + (idx % S)] = Ww[idx];
    }
    __syncthreads();

    // ---- build comb tile: comb[r][s] = h_left + h_right ----
    if (LEAF) {
        // children are leaves: h = relu(t*Qw + Qb), computed on the fly.
        for (int idx = tid; idx < TM * S; idx += NTHREADS) {
            int r = idx / S, s = idx % S;
            int g = baseRow + r;
            int b = g >> d;
            int n = g & (lvl - 1);
            const float* tb = times + (long)b * NNODES;
            float tL = tb[2 * lvl - 1 + 2 * n];
            float tR = tb[2 * lvl + 2 * n];
            float qw = Qw_s[s], qb = Qb_s[s];
            comb_s[r * SP + s] = fmaxf(fmaf(tL, qw, qb), 0.f)
                               + fmaxf(fmaf(tR, qw, qb), 0.f);
        }
    } else {
        for (int idx = tid; idx < TM * S; idx += NTHREADS) {
            int r = idx / S, s = idx % S;
            long g = baseRow + r;
            comb_s[r * SP + s] = prev[(2 * g) * S + s] + prev[(2 * g + 1) * S + s];
        }
    }
    __syncthreads();

    // ---- register-blocked GEMM: 4 nodes x 5 outputs per thread ----
    const int i  = tid & 7;        // node group 0..7
    const int j  = tid >> 3;       // out group  0..19
    const int r0 = i * 4;
    const int c0 = j * 5;

    float acc[4][5];
#pragma unroll
    for (int r = 0; r < 4; r++)
#pragma unroll
        for (int c = 0; c < 5; c++) acc[r][c] = 0.f;

    const float* cp = comb_s + r0 * SP;
    const float* wp = Ww_s + c0 * SP;

#pragma unroll 2
    for (int k = 0; k < S; k++) {
        float a[4], b[5];
#pragma unroll
        for (int r = 0; r < 4; r++) a[r] = cp[r * SP + k];
#pragma unroll
        for (int c = 0; c < 5; c++) b[c] = wp[c * SP + k];
#pragma unroll
        for (int r = 0; r < 4; r++)
#pragma unroll
            for (int c = 0; c < 5; c++)
                acc[r][c] = fmaf(a[r], b[c], acc[r][c]);
    }

    // ---- epilogue: + Wb + t*Qw + Qb, relu ----
    float tval[4];
#pragma unroll
    for (int r = 0; r < 4; r++) {
        int g = baseRow + r0 + r;
        int b = g >> d;
        int n = g & (lvl - 1);
        tval[r] = times[(long)b * NNODES + (lvl - 1) + n];
    }

    float hv[4][5];
#pragma unroll
    for (int r = 0; r < 4; r++) {
#pragma unroll
        for (int c = 0; c < 5; c++) {
            int o = c0 + c;
            float h = acc[r][c] + Wb_s[o] + fmaf(tval[r], Qw_s[o], Qb_s[o]);
            hv[r][c] = fmaxf(h, 0.f);
        }
    }

    if (!ROOT) {
#pragma unroll
        for (int r = 0; r < 4; r++) {
            long g = baseRow + r0 + r;
#pragma unroll
            for (int c = 0; c < 5; c++) {
                cur[g * S + (c0 + c)] = hv[r][c];
            }
        }
    } else {
        // stash root h in smem (reuse comb tile), then project to 5 params
        __syncthreads();
#pragma unroll
        for (int r = 0; r < 4; r++)
#pragma unroll
            for (int c = 0; c < 5; c++)
                comb_s[(r0 + r) * SP + (c0 + c)] = hv[r][c];
        __syncthreads();

        // 32 trees x 5 params = 160 outputs = one per thread
        int tr = tid / 5;
        int p  = tid % 5;
        float a2 = Pb[p];
        const float* pw = Pw + p * S;
        const float* hs = comb_s + tr * SP;
#pragma unroll 4
        for (int o = 0; o < S; o++) a2 = fmaf(hs[o], pw[o], a2);
        out[(long)(baseRow + tr) * 5 + p] = a2;
    }
}

extern "C" void kernel_launch(void* const* d_in, const int* in_sizes, int n_in,
                              void* d_out, int out_size)
{
    const float* times = (const float*)d_in[0];
    const float* Qw    = (const float*)d_in[1];
    const float* Qb    = (const float*)d_in[2];
    const float* Ww    = (const float*)d_in[3];
    const float* Wb    = (const float*)d_in[4];
    const float* Pw    = (const float*)d_in[5];
    const float* Pb    = (const float*)d_in[6];
    float* out = (float*)d_out;

    float *pA = nullptr, *pB = nullptr;
    cudaGetSymbolAddress((void**)&pA, g_bufA);
    cudaGetSymbolAddress((void**)&pB, g_bufB);

    cudaFuncSetAttribute(level_kernel<true, false>,
                         cudaFuncAttributeMaxDynamicSharedMemorySize, SMEM_BYTES);
    cudaFuncSetAttribute(level_kernel<false, false>,
                         cudaFuncAttributeMaxDynamicSharedMemorySize, SMEM_BYTES);
    cudaFuncSetAttribute(level_kernel<false, true>,
                         cudaFuncAttributeMaxDynamicSharedMemorySize, SMEM_BYTES);

    // Level 8: leaves fused, writes g_bufA
    level_kernel<true, false><<<(NTREES * 256) / TM, NTHREADS, SMEM_BYTES>>>(
        times, Qw, Qb, Ww, Wb, Pw, Pb, nullptr, pA, nullptr, 8);

    // Levels 7..1: ping-pong A<->B
    float* prev = pA;
    for (int d = 7; d >= 1; --d) {
        float* cur = (prev == pA) ? pB : pA;
        level_kernel<false, false><<<(NTREES << d) / TM, NTHREADS, SMEM_BYTES>>>(
            times, Qw, Qb, Ww, Wb, Pw, Pb, prev, cur, nullptr, d);
        prev = cur;
    }

    // Level 0: root + projection, writes d_out
    level_kernel<false, true><<<NTREES / TM, NTHREADS, SMEM_BYTES>>>(
        times, Qw, Qb, Ww, Wb, Pw, Pb, prev, nullptr, out, 0);
}